// round 4
// baseline (speedup 1.0000x reference)
#include <cuda_runtime.h>
#include <math.h>

#define NNODES 20000
#define NEDGES 40000
#define NGRAPH 1000

// ---------------- scratch (no allocations allowed: static __device__) ----------------
__device__ float g_h[NEDGES * 128];      // edge MLP hidden  (20.5 MB)
__device__ float g_bufA[NNODES * 64];    // node features ping
__device__ float g_bufB[NNODES * 64];    // node features pong
__device__ float g_pool[NGRAPH * 64];    // pooled sums
__device__ float g_cnt[NGRAPH];          // node counts per graph

// ---------------- edge MLP first layer: h = relu(edge_attr @ w1 + b1) ----------------
__global__ void h_kernel(const float* __restrict__ ea, const float* __restrict__ w1,
                         const float* __restrict__ b1, float* __restrict__ h) {
    int idx = blockIdx.x * blockDim.x + threadIdx.x;
    if (idx >= NEDGES * 128) return;
    int e = idx >> 7;
    int j = idx & 127;
    const float* a = ea + e * 5;
    float acc = b1[j];
    acc += a[0] * w1[0 * 128 + j];
    acc += a[1] * w1[1 * 128 + j];
    acc += a[2] * w1[2 * 128 + j];
    acc += a[3] * w1[3 * 128 + j];
    acc += a[4] * w1[4 * 128 + j];
    h[idx] = fmaxf(acc, 0.0f);
}

// ---------------- out = x @ root + bias (seeds the aggregation buffer) ----------------
template <int MI, int MO>
__global__ void root_kernel(const float* __restrict__ x, const float* __restrict__ root,
                            const float* __restrict__ bias, float* __restrict__ out) {
    int idx = blockIdx.x * blockDim.x + threadIdx.x;
    if (idx >= NNODES * MO) return;
    int n = idx / MO;
    int o = idx % MO;
    float acc = bias[o];
#pragma unroll
    for (int i = 0; i < MI; i++) acc += x[n * MI + i] * root[i * MO + o];
    out[idx] = acc;
}

// ---------------- fused edge message GEMM + scatter-add ----------------
// msg[e,o] = sum_{k < 129*MI} P[e,k] * W2v[k,o]
//   k = c*MI + i, c<128:  P = h[e,c]*x_src[e,i],  W2v = w2 flat [k*MO+o]
//   c==128 (b2 rows):     P = x_src[e,i],          W2v = b2[i*MO+o]
// then atomicAdd into out[dst[e]*MO + o].
template <int MI, int MO>
__global__ __launch_bounds__(128)
void edge_kernel(const float* __restrict__ h, const float* __restrict__ x,
                 const float* __restrict__ w2, const float* __restrict__ b2,
                 const int* __restrict__ src, const int* __restrict__ dst,
                 float* __restrict__ out) {
    constexpr int BM = 64;                 // edges per block
    constexpr int BK = 32;                 // K chunk
    constexpr int THREADS = 128;
    constexpr int KTOT = 129 * MI;
    constexpr int TN = 4;                  // outputs per thread, o-dim
    constexpr int TCOL = MO / TN;          // threads along o (8 or 16)
    constexpr int TROW = THREADS / TCOL;   // threads along e (16 or 8)
    constexpr int TM = BM / TROW;          // outputs per thread, e-dim (4 or 8)

    __shared__ __align__(16) float x_s[BM][MI + 1];   // gathered src features
    __shared__ __align__(16) float P_s[BK][BM];       // on-the-fly P chunk
    __shared__ __align__(16) float W_s[BK][MO];       // w2 chunk
    __shared__ int src_s[BM];

    const int tid = threadIdx.x;
    const int e0 = blockIdx.x * BM;

    if (tid < BM) src_s[tid] = src[e0 + tid];
    __syncthreads();

    for (int idx = tid; idx < BM * MI; idx += THREADS) {
        int e = idx / MI;
        int i = idx - e * MI;
        x_s[e][i] = x[src_s[e] * MI + i];
    }
    __syncthreads();

    const int og = tid % TCOL;
    const int eg = tid / TCOL;
    const int oBase = og * TN;
    const int eBase = eg * TM;

    float acc[TM][TN];
#pragma unroll
    for (int m = 0; m < TM; m++)
#pragma unroll
        for (int n = 0; n < TN; n++) acc[m][n] = 0.0f;

    const float* __restrict__ hrow = h + (size_t)e0 * 128;

    for (int k0 = 0; k0 < KTOT; k0 += BK) {
        // ---- build P chunk (h read through L1/L2; only ~BK/MI distinct c per chunk) ----
#pragma unroll
        for (int r = 0; r < (BM * BK) / THREADS; r++) {   // 16 iters
            int idx = tid + r * THREADS;
            int e = idx & (BM - 1);
            int kk = idx >> 6;
            int k = k0 + kk;
            float v = 0.0f;
            if (k < KTOT) {
                int c = k / MI;
                int i = k - c * MI;
                float hv = (c < 128) ? hrow[e * 128 + c] : 1.0f;
                v = hv * x_s[e][i];
            }
            P_s[kk][e] = v;
        }
        // ---- load W chunk ----
#pragma unroll
        for (int r = 0; r < (BK * MO) / THREADS; r++) {   // 8 or 16 iters
            int idx = tid + r * THREADS;
            int o = idx & (MO - 1);
            int kk = idx / MO;
            int k = k0 + kk;
            float v = 0.0f;
            if (k < 128 * MI)      v = w2[(size_t)k * MO + o];
            else if (k < KTOT)     v = b2[(k - 128 * MI) * MO + o];
            W_s[kk][o] = v;
        }
        __syncthreads();

        // ---- register-tiled inner product ----
#pragma unroll
        for (int kk = 0; kk < BK; kk++) {
            float p[TM];
            float w[TN];
#pragma unroll
            for (int m4 = 0; m4 < TM / 4; m4++) {
                float4 pv = *reinterpret_cast<const float4*>(&P_s[kk][eBase + m4 * 4]);
                p[m4 * 4 + 0] = pv.x; p[m4 * 4 + 1] = pv.y;
                p[m4 * 4 + 2] = pv.z; p[m4 * 4 + 3] = pv.w;
            }
            float4 wv = *reinterpret_cast<const float4*>(&W_s[kk][oBase]);
            w[0] = wv.x; w[1] = wv.y; w[2] = wv.z; w[3] = wv.w;
#pragma unroll
            for (int m = 0; m < TM; m++)
#pragma unroll
                for (int n = 0; n < TN; n++) acc[m][n] += p[m] * w[n];
        }
        __syncthreads();
    }

    // ---- scatter-add into destination nodes ----
#pragma unroll
    for (int m = 0; m < TM; m++) {
        int d = dst[e0 + eBase + m];
        float* o = out + (size_t)d * MO + oBase;
#pragma unroll
        for (int n = 0; n < TN; n++) atomicAdd(o + n, acc[m][n]);
    }
}

// ---------------- elementwise ELU (in place) ----------------
__global__ void elu_kernel(float* __restrict__ x, int n) {
    int i = blockIdx.x * blockDim.x + threadIdx.x;
    if (i >= n) return;
    float v = x[i];
    x[i] = v > 0.0f ? v : (expf(v) - 1.0f);
}

// ---------------- pooling ----------------
__global__ void zero_pool_kernel() {
    int i = blockIdx.x * blockDim.x + threadIdx.x;
    if (i < NGRAPH * 64) g_pool[i] = 0.0f;
    if (i < NGRAPH) g_cnt[i] = 0.0f;
}

__global__ void pool_kernel(const float* __restrict__ x, const int* __restrict__ batch) {
    int idx = blockIdx.x * blockDim.x + threadIdx.x;
    if (idx >= NNODES * 64) return;
    int n = idx >> 6;
    int o = idx & 63;
    int g = batch[n];
    atomicAdd(&g_pool[g * 64 + o], x[idx]);
    if (o == 0) atomicAdd(&g_cnt[g], 1.0f);
}

// ---------------- per-graph MLP head ----------------
__global__ void mlp_kernel(const float* __restrict__ fc1w, const float* __restrict__ fc1b,
                           const float* __restrict__ fc2w, const float* __restrict__ fc2b,
                           const float* __restrict__ fc3w, const float* __restrict__ fc3b,
                           float* __restrict__ out) {
    __shared__ float xg[64];
    __shared__ float y1[32];
    __shared__ float y2[16];
    int g = blockIdx.x;
    int t = threadIdx.x;

    float c = fmaxf(g_cnt[g], 1.0f);
    xg[t] = g_pool[g * 64 + t] / c;
    __syncthreads();

    if (t < 32) {
        float a = fc1b[t];
#pragma unroll
        for (int i = 0; i < 64; i++) a += xg[i] * fc1w[i * 32 + t];
        y1[t] = a > 0.0f ? a : (expf(a) - 1.0f);
    }
    __syncthreads();
    if (t < 16) {
        float a = fc2b[t];
#pragma unroll
        for (int i = 0; i < 32; i++) a += y1[i] * fc2w[i * 16 + t];
        y2[t] = a > 0.0f ? a : (expf(a) - 1.0f);
    }
    __syncthreads();
    if (t == 0) {
        float a = fc3b[0];
#pragma unroll
        for (int i = 0; i < 16; i++) a += y2[i] * fc3w[i];
        out[g] = a;
    }
}

// ---------------- launch ----------------
extern "C" void kernel_launch(void* const* d_in, const int* in_sizes, int n_in,
                              void* d_out, int out_size) {
    const float* x_in  = (const float*)d_in[0];
    const int*   ei    = (const int*)d_in[1];
    const float* ea    = (const float*)d_in[2];
    const int*   batch = (const int*)d_in[3];

    const float* w1[3]   = {(const float*)d_in[4],  (const float*)d_in[10], (const float*)d_in[16]};
    const float* b1[3]   = {(const float*)d_in[5],  (const float*)d_in[11], (const float*)d_in[17]};
    const float* w2[3]   = {(const float*)d_in[6],  (const float*)d_in[12], (const float*)d_in[18]};
    const float* b2[3]   = {(const float*)d_in[7],  (const float*)d_in[13], (const float*)d_in[19]};
    const float* root[3] = {(const float*)d_in[8],  (const float*)d_in[14], (const float*)d_in[20]};
    const float* bias[3] = {(const float*)d_in[9],  (const float*)d_in[15], (const float*)d_in[21]};

    const float* fc1w = (const float*)d_in[22];
    const float* fc1b = (const float*)d_in[23];
    const float* fc2w = (const float*)d_in[24];
    const float* fc2b = (const float*)d_in[25];
    const float* fc3w = (const float*)d_in[26];
    const float* fc3b = (const float*)d_in[27];

    const int* src = ei;            // edge_index[0]
    const int* dst = ei + NEDGES;   // edge_index[1]

    float *hbuf, *bufA, *bufB;
    cudaGetSymbolAddress((void**)&hbuf, g_h);
    cudaGetSymbolAddress((void**)&bufA, g_bufA);
    cudaGetSymbolAddress((void**)&bufB, g_bufB);

    const int HT = (NEDGES * 128 + 255) / 256;

    // ---- layer 0: 13 -> 32 ----
    h_kernel<<<HT, 256>>>(ea, w1[0], b1[0], hbuf);
    root_kernel<13, 32><<<(NNODES * 32 + 255) / 256, 256>>>(x_in, root[0], bias[0], bufA);
    edge_kernel<13, 32><<<NEDGES / 64, 128>>>(hbuf, x_in, w2[0], b2[0], src, dst, bufA);
    elu_kernel<<<(NNODES * 32 + 255) / 256, 256>>>(bufA, NNODES * 32);

    // ---- layer 1: 32 -> 64 ----
    h_kernel<<<HT, 256>>>(ea, w1[1], b1[1], hbuf);
    root_kernel<32, 64><<<(NNODES * 64 + 255) / 256, 256>>>(bufA, root[1], bias[1], bufB);
    edge_kernel<32, 64><<<NEDGES / 64, 128>>>(hbuf, bufA, w2[1], b2[1], src, dst, bufB);
    elu_kernel<<<(NNODES * 64 + 255) / 256, 256>>>(bufB, NNODES * 64);

    // ---- layer 2: 64 -> 64 ----
    h_kernel<<<HT, 256>>>(ea, w1[2], b1[2], hbuf);
    root_kernel<64, 64><<<(NNODES * 64 + 255) / 256, 256>>>(bufB, root[2], bias[2], bufA);
    edge_kernel<64, 64><<<NEDGES / 64, 128>>>(hbuf, bufB, w2[2], b2[2], src, dst, bufA);
    elu_kernel<<<(NNODES * 64 + 255) / 256, 256>>>(bufA, NNODES * 64);

    // ---- pooling + MLP head ----
    zero_pool_kernel<<<(NGRAPH * 64 + 255) / 256, 256>>>();
    pool_kernel<<<(NNODES * 64 + 255) / 256, 256>>>(bufA, batch);
    mlp_kernel<<<NGRAPH, 64>>>(fc1w, fc1b, fc2w, fc2b, fc3w, fc3b, (float*)d_out);
}

// round 7
// speedup vs baseline: 1.5910x; 1.5910x over previous
#include <cuda_runtime.h>
#include <math.h>

#define NNODES 20000
#define NEDGES 40000
#define NGRAPH 1000

// ---------------- scratch (no allocations allowed: static __device__) ----------------
__device__ float g_h[NEDGES * 128];      // edge MLP hidden  (20.5 MB)
__device__ float g_bufA[NNODES * 64];    // node features ping
__device__ float g_bufB[NNODES * 64];    // node features pong
__device__ float g_S[NNODES * 64];       // per-node sum of gathered x (for b2 term)
__device__ float g_pool[NGRAPH * 64];    // pooled sums
__device__ float g_cnt[NGRAPH];          // node counts per graph

// ---------------- f32x2 packed-math helpers (sm_100+) ----------------
__device__ __forceinline__ void ffma2(unsigned long long& acc,
                                      unsigned long long a, unsigned long long b) {
    asm("fma.rn.f32x2 %0, %1, %2, %0;" : "+l"(acc) : "l"(a), "l"(b));
}
__device__ __forceinline__ unsigned long long pack2(float v) {
    unsigned long long d;
    asm("mov.b64 %0, {%1, %2};" : "=l"(d) : "f"(v), "f"(v));
    return d;
}

// ---------------- edge MLP first layer: h = relu(edge_attr @ w1 + b1) ----------------
__global__ void h_kernel(const float* __restrict__ ea, const float* __restrict__ w1,
                         const float* __restrict__ b1, float* __restrict__ h) {
    int idx = blockIdx.x * blockDim.x + threadIdx.x;
    if (idx >= NEDGES * 128) return;
    int e = idx >> 7;
    int j = idx & 127;
    const float* a = ea + e * 5;
    float acc = b1[j];
    acc += a[0] * w1[0 * 128 + j];
    acc += a[1] * w1[1 * 128 + j];
    acc += a[2] * w1[2 * 128 + j];
    acc += a[3] * w1[3 * 128 + j];
    acc += a[4] * w1[4 * 128 + j];
    h[idx] = fmaxf(acc, 0.0f);
}

// ---------------- out = x @ root + bias (seeds the aggregation buffer) ----------------
template <int MI, int MO>
__global__ void root_kernel(const float* __restrict__ x, const float* __restrict__ root,
                            const float* __restrict__ bias, float* __restrict__ out) {
    int idx = blockIdx.x * blockDim.x + threadIdx.x;
    if (idx >= NNODES * MO) return;
    int n = idx / MO;
    int o = idx % MO;
    float acc = bias[o];
#pragma unroll
    for (int i = 0; i < MI; i++) acc += x[n * MI + i] * root[i * MO + o];
    out[idx] = acc;
}

// ---------------- b2 term: S[d] = sum_{e: dst=d} x[src[e]] ; out += S @ B2 ----------
__global__ void zero_kernel(float* __restrict__ p, int n) {
    int i = blockIdx.x * blockDim.x + threadIdx.x;
    if (i < n) p[i] = 0.0f;
}

template <int MI>
__global__ void scatter_x_kernel(const float* __restrict__ x, const int* __restrict__ src,
                                 const int* __restrict__ dst, float* __restrict__ S) {
    int idx = blockIdx.x * blockDim.x + threadIdx.x;
    if (idx >= NEDGES * MI) return;
    int e = idx / MI;
    int i = idx - e * MI;
    atomicAdd(&S[dst[e] * MI + i], x[src[e] * MI + i]);
}

template <int MI, int MO>
__global__ void sb2_kernel(const float* __restrict__ S, const float* __restrict__ b2,
                           float* __restrict__ out) {
    int idx = blockIdx.x * blockDim.x + threadIdx.x;
    if (idx >= NNODES * MO) return;
    int n = idx / MO;
    int o = idx - n * MO;
    float a = 0.0f;
#pragma unroll
    for (int i = 0; i < MI; i++) a += S[n * MI + i] * b2[i * MO + o];
    out[idx] += a;
}

// ---------------- fused edge message GEMM + scatter-add ----------------
// msg[e,o] = sum_i sum_c (h[e,c] * x[src[e],i]) * w2[c, i*MO+o]
// i-outer/c-chunk decomposition: P-chunk built with COALESCED h loads
// (lane -> c) and broadcast x loads. f32x2 packed FMA in the inner product.
template <int MI, int MO, int KSPLIT>
__global__ __launch_bounds__((MO / 8) * 16)
void edge_kernel(const float* __restrict__ h, const float* __restrict__ x,
                 const float* __restrict__ w2,
                 const int* __restrict__ src, const int* __restrict__ dst,
                 float* __restrict__ out) {
    constexpr int BM = 128;                // edges per block
    constexpr int BK = 32;                 // c chunk
    constexpr int TN = 8;                  // o per thread (4 f32x2 pairs)
    constexpr int TM = 8;                  // edges per thread
    constexpr int NP = TN / 2;
    constexpr int TCOL = MO / TN;          // 8 (MO=64) or 4 (MO=32)
    constexpr int TROW = BM / TM;          // 16
    constexpr int THREADS = TCOL * TROW;   // 128 or 64
    constexpr int EROWS = THREADS / 32;    // e-rows built per pass
    constexpr int EBLKS = (NEDGES + BM - 1) / BM;   // 313
    constexpr int LOGMO = (MO == 64) ? 6 : 5;

    __shared__ float P_s[BM][BK + 1];               // padded: conflict-free
    __shared__ __align__(16) float W_s[BK][MO];
    __shared__ int src_s[BM];

    const int tid = threadIdx.x;
    const int eb = blockIdx.x % EBLKS;
    const int ks = blockIdx.x / EBLKS;
    const int e0 = eb * BM;
    const int i0 = (MI * ks) / KSPLIT;
    const int i1 = (MI * (ks + 1)) / KSPLIT;

    for (int t = tid; t < BM; t += THREADS)
        src_s[t] = src[min(e0 + t, NEDGES - 1)];
    __syncthreads();

    const int og = tid % TCOL;
    const int eg = tid / TCOL;
    const int oBase = og * TN;
    const int eBase = eg * TM;
    const int lane = tid & 31;
    const int erow = tid >> 5;

    unsigned long long acc[TM][NP];
#pragma unroll
    for (int m = 0; m < TM; m++)
#pragma unroll
        for (int n = 0; n < NP; n++) acc[m][n] = 0ull;

#pragma unroll 1
    for (int c0 = 0; c0 < 128; c0 += BK) {
#pragma unroll 1
        for (int i = i0; i < i1; i++) {
            // ---- build P chunk: coalesced h (lane->c), broadcast x ----
#pragma unroll
            for (int r = 0; r < BM / EROWS; r++) {
                int e = r * EROWS + erow;
                int gc = min(e0 + e, NEDGES - 1);
                float hv = __ldg(&h[(size_t)gc * 128 + c0 + lane]);
                float xv = __ldg(&x[src_s[e] * MI + i]);
                P_s[e][lane] = hv * xv;
            }
            // ---- load W chunk: w2[c0+kk][i*MO+o], coalesced over o ----
#pragma unroll
            for (int r = 0; r < (BK * MO) / THREADS; r++) {
                int idx = tid + r * THREADS;
                int o = idx & (MO - 1);
                int kk = idx >> LOGMO;
                W_s[kk][o] = __ldg(&w2[(size_t)(c0 + kk) * (MI * MO) + i * MO + o]);
            }
            __syncthreads();

            // ---- register-tiled inner product, f32x2 packed FMA ----
#pragma unroll
            for (int kk = 0; kk < BK; kk++) {
                const ulonglong2* wp =
                    reinterpret_cast<const ulonglong2*>(&W_s[kk][oBase]);
                ulonglong2 wa = wp[0];
                ulonglong2 wb = wp[1];
                unsigned long long w[NP] = {wa.x, wa.y, wb.x, wb.y};
#pragma unroll
                for (int m = 0; m < TM; m++) {
                    unsigned long long pd = pack2(P_s[eBase + m][kk]);
#pragma unroll
                    for (int n = 0; n < NP; n++) ffma2(acc[m][n], pd, w[n]);
                }
            }
            __syncthreads();
        }
    }

    // ---- scatter-add into destination nodes ----
#pragma unroll
    for (int m = 0; m < TM; m++) {
        int ge = e0 + eBase + m;
        if (ge < NEDGES) {
            int d = dst[ge];
            float* op = out + (size_t)d * MO + oBase;
#pragma unroll
            for (int n = 0; n < NP; n++) {
                unsigned long long v = acc[m][n];
                atomicAdd(op + 2 * n,     __uint_as_float((unsigned)(v & 0xffffffffULL)));
                atomicAdd(op + 2 * n + 1, __uint_as_float((unsigned)(v >> 32)));
            }
        }
    }
}

// ---------------- elementwise ELU (in place) ----------------
__global__ void elu_kernel(float* __restrict__ x, int n) {
    int i = blockIdx.x * blockDim.x + threadIdx.x;
    if (i >= n) return;
    float v = x[i];
    x[i] = v > 0.0f ? v : (expf(v) - 1.0f);
}

// ---------------- pooling ----------------
__global__ void zero_pool_kernel() {
    int i = blockIdx.x * blockDim.x + threadIdx.x;
    if (i < NGRAPH * 64) g_pool[i] = 0.0f;
    if (i < NGRAPH) g_cnt[i] = 0.0f;
}

__global__ void pool_kernel(const float* __restrict__ x, const int* __restrict__ batch) {
    int idx = blockIdx.x * blockDim.x + threadIdx.x;
    if (idx >= NNODES * 64) return;
    int n = idx >> 6;
    int o = idx & 63;
    int g = batch[n];
    atomicAdd(&g_pool[g * 64 + o], x[idx]);
    if (o == 0) atomicAdd(&g_cnt[g], 1.0f);
}

// ---------------- per-graph MLP head ----------------
__global__ void mlp_kernel(const float* __restrict__ fc1w, const float* __restrict__ fc1b,
                           const float* __restrict__ fc2w, const float* __restrict__ fc2b,
                           const float* __restrict__ fc3w, const float* __restrict__ fc3b,
                           float* __restrict__ out) {
    __shared__ float xg[64];
    __shared__ float y1[32];
    __shared__ float y2[16];
    int g = blockIdx.x;
    int t = threadIdx.x;

    float c = fmaxf(g_cnt[g], 1.0f);
    xg[t] = g_pool[g * 64 + t] / c;
    __syncthreads();

    if (t < 32) {
        float a = fc1b[t];
#pragma unroll
        for (int i = 0; i < 64; i++) a += xg[i] * fc1w[i * 32 + t];
        y1[t] = a > 0.0f ? a : (expf(a) - 1.0f);
    }
    __syncthreads();
    if (t < 16) {
        float a = fc2b[t];
#pragma unroll
        for (int i = 0; i < 32; i++) a += y1[i] * fc2w[i * 16 + t];
        y2[t] = a > 0.0f ? a : (expf(a) - 1.0f);
    }
    __syncthreads();
    if (t == 0) {
        float a = fc3b[0];
#pragma unroll
        for (int i = 0; i < 16; i++) a += y2[i] * fc3w[i];
        out[g] = a;
    }
}

// ---------------- launch ----------------
extern "C" void kernel_launch(void* const* d_in, const int* in_sizes, int n_in,
                              void* d_out, int out_size) {
    const float* x_in  = (const float*)d_in[0];
    const int*   ei    = (const int*)d_in[1];
    const float* ea    = (const float*)d_in[2];
    const int*   batch = (const int*)d_in[3];

    const float* w1[3]   = {(const float*)d_in[4],  (const float*)d_in[10], (const float*)d_in[16]};
    const float* b1[3]   = {(const float*)d_in[5],  (const float*)d_in[11], (const float*)d_in[17]};
    const float* w2[3]   = {(const float*)d_in[6],  (const float*)d_in[12], (const float*)d_in[18]};
    const float* b2[3]   = {(const float*)d_in[7],  (const float*)d_in[13], (const float*)d_in[19]};
    const float* root[3] = {(const float*)d_in[8],  (const float*)d_in[14], (const float*)d_in[20]};
    const float* bias[3] = {(const float*)d_in[9],  (const float*)d_in[15], (const float*)d_in[21]};

    const float* fc1w = (const float*)d_in[22];
    const float* fc1b = (const float*)d_in[23];
    const float* fc2w = (const float*)d_in[24];
    const float* fc2b = (const float*)d_in[25];
    const float* fc3w = (const float*)d_in[26];
    const float* fc3b = (const float*)d_in[27];

    const int* src = ei;            // edge_index[0]
    const int* dst = ei + NEDGES;   // edge_index[1]

    float *hbuf, *bufA, *bufB, *Sbuf;
    cudaGetSymbolAddress((void**)&hbuf, g_h);
    cudaGetSymbolAddress((void**)&bufA, g_bufA);
    cudaGetSymbolAddress((void**)&bufB, g_bufB);
    cudaGetSymbolAddress((void**)&Sbuf, g_S);

    const int HT = (NEDGES * 128 + 255) / 256;
    const int EBLKS = (NEDGES + 127) / 128;   // 313

    // ---- layer 0: 13 -> 32 ----
    h_kernel<<<HT, 256>>>(ea, w1[0], b1[0], hbuf);
    root_kernel<13, 32><<<(NNODES * 32 + 255) / 256, 256>>>(x_in, root[0], bias[0], bufA);
    zero_kernel<<<(NNODES * 13 + 255) / 256, 256>>>(Sbuf, NNODES * 13);
    scatter_x_kernel<13><<<(NEDGES * 13 + 255) / 256, 256>>>(x_in, src, dst, Sbuf);
    sb2_kernel<13, 32><<<(NNODES * 32 + 255) / 256, 256>>>(Sbuf, b2[0], bufA);
    edge_kernel<13, 32, 2><<<EBLKS * 2, 64>>>(hbuf, x_in, w2[0], src, dst, bufA);
    elu_kernel<<<(NNODES * 32 + 255) / 256, 256>>>(bufA, NNODES * 32);

    // ---- layer 1: 32 -> 64 ----
    h_kernel<<<HT, 256>>>(ea, w1[1], b1[1], hbuf);
    root_kernel<32, 64><<<(NNODES * 64 + 255) / 256, 256>>>(bufA, root[1], bias[1], bufB);
    zero_kernel<<<(NNODES * 32 + 255) / 256, 256>>>(Sbuf, NNODES * 32);
    scatter_x_kernel<32><<<(NEDGES * 32 + 255) / 256, 256>>>(bufA, src, dst, Sbuf);
    sb2_kernel<32, 64><<<(NNODES * 64 + 255) / 256, 256>>>(Sbuf, b2[1], bufB);
    edge_kernel<32, 64, 2><<<EBLKS * 2, 128>>>(hbuf, bufA, w2[1], src, dst, bufB);
    elu_kernel<<<(NNODES * 64 + 255) / 256, 256>>>(bufB, NNODES * 64);

    // ---- layer 2: 64 -> 64 ----
    h_kernel<<<HT, 256>>>(ea, w1[2], b1[2], hbuf);
    root_kernel<64, 64><<<(NNODES * 64 + 255) / 256, 256>>>(bufB, root[2], bias[2], bufA);
    zero_kernel<<<(NNODES * 64 + 255) / 256, 256>>>(Sbuf, NNODES * 64);
    scatter_x_kernel<64><<<(NEDGES * 64 + 255) / 256, 256>>>(bufB, src, dst, Sbuf);
    sb2_kernel<64, 64><<<(NNODES * 64 + 255) / 256, 256>>>(Sbuf, b2[2], bufA);
    edge_kernel<64, 64, 2><<<EBLKS * 2, 128>>>(hbuf, bufB, w2[2], src, dst, bufA);
    elu_kernel<<<(NNODES * 64 + 255) / 256, 256>>>(bufA, NNODES * 64);

    // ---- pooling + MLP head ----
    zero_pool_kernel<<<(NGRAPH * 64 + 255) / 256, 256>>>();
    pool_kernel<<<(NNODES * 64 + 255) / 256, 256>>>(bufA, batch);
    mlp_kernel<<<NGRAPH, 64>>>(fc1w, fc1b, fc2w, fc2b, fc3w, fc3b, (float*)d_out);
}

// round 15
// speedup vs baseline: 4.1771x; 2.6255x over previous
#include <cuda_runtime.h>
#include <cuda_bf16.h>
#include <cstdint>
#include <math.h>

#define NNODES 20000
#define NEDGES 40000
#define NGRAPH 1000
#define EBLKS 313              // ceil(40000/128)

typedef unsigned long long ull;

// ---------------- scratch (static __device__: no allocations allowed) ----------------
__device__ float g_ht[128 * NEDGES];                 // edge MLP hidden, TRANSPOSED [c][e]
__device__ float g_bufA[NNODES * 64];
__device__ float g_bufB[NNODES * 64];
__device__ float g_S[NNODES * 64];
__device__ float g_pool[NGRAPH * 64];
__device__ float g_cnt[NGRAPH];
__device__ __align__(16) __nv_bfloat16 g_w2t_hi[128 * 64 * 64];  // pre-swizzled B-tile images
__device__ __align__(16) __nv_bfloat16 g_w2t_lo[128 * 64 * 64];

// ================= PTX helpers (plain sm_80+/sm_90 PTX: no 'a'-gated features) =====
__device__ __forceinline__ uint32_t smem_to_u32(const void* p) {
    uint32_t a;
    asm("{ .reg .u64 t; cvta.to.shared.u64 t, %1; cvt.u32.u64 %0, t; }" : "=r"(a) : "l"(p));
    return a;
}
#define LDSM4(r, addr) \
    asm volatile("ldmatrix.sync.aligned.m8n8.x4.shared.b16 {%0,%1,%2,%3}, [%4];" \
        : "=r"((r)[0]), "=r"((r)[1]), "=r"((r)[2]), "=r"((r)[3]) : "r"(addr))
#define MMA_BF16(d, a, b) \
    asm volatile("mma.sync.aligned.m16n8k16.row.col.f32.bf16.bf16.f32 " \
        "{%0,%1,%2,%3}, {%4,%5,%6,%7}, {%8,%9}, {%0,%1,%2,%3};" \
        : "+f"((d)[0]), "+f"((d)[1]), "+f"((d)[2]), "+f"((d)[3]) \
        : "r"((a)[0]), "r"((a)[1]), "r"((a)[2]), "r"((a)[3]), "r"((b)[0]), "r"((b)[1]))

// packed f32x2 + bit tricks
__device__ __forceinline__ ull pack2(float v) {
    ull d; asm("mov.b64 %0, {%1, %2};" : "=l"(d) : "f"(v), "f"(v)); return d;
}
__device__ __forceinline__ ull mul2(ull a, ull b) {
    ull d; asm("mul.rn.f32x2 %0, %1, %2;" : "=l"(d) : "l"(a), "l"(b)); return d;
}
__device__ __forceinline__ void ffma2(ull& acc, ull a, ull b) {
    asm("fma.rn.f32x2 %0, %1, %2, %0;" : "+l"(acc) : "l"(a), "l"(b));
}
__device__ __forceinline__ void unpack2(ull v, unsigned& a, unsigned& b) {
    asm("mov.b64 {%0, %1}, %2;" : "=r"(a), "=r"(b) : "l"(v));
}
__device__ __forceinline__ unsigned prmt7632(unsigned a, unsigned b) {
    unsigned d; asm("prmt.b32 %0, %1, %2, 0x7632;" : "=r"(d) : "r"(a), "r"(b)); return d;
}
#define CVT_BF16X2(res, a, b) \
    asm("cvt.rn.bf16x2.f32 %0, %1, %2;" : "=r"(res) : "f"(b), "f"(a))
#define STSV2(addr, r0, r1) \
    asm volatile("st.shared.v2.b32 [%0], {%1, %2};" :: "r"(addr), "r"(r0), "r"(r1) : "memory")

// ---------------- edge MLP first layer (TRANSPOSED output): ht[c][e] ----------------
__global__ void h_kernel(const float* __restrict__ ea, const float* __restrict__ w1,
                         const float* __restrict__ b1, float* __restrict__ ht) {
    int idx = blockIdx.x * blockDim.x + threadIdx.x;
    if (idx >= 128 * NEDGES) return;
    int c = idx / NEDGES;
    int e = idx - c * NEDGES;
    const float* a = ea + e * 5;
    float acc = b1[c];
    acc += a[0] * w1[0 * 128 + c];
    acc += a[1] * w1[1 * 128 + c];
    acc += a[2] * w1[2 * 128 + c];
    acc += a[3] * w1[3 * 128 + c];
    acc += a[4] * w1[4 * 128 + c];
    ht[idx] = fmaxf(acc, 0.0f);
}

// ---------------- w2 -> pre-swizzled bf16 hi/lo B-tile images ----------------
// Global layout: [chunk][byte-image of (MO rows x 128B) SW128 tile], rows = o, cols = kk.
// tile element (o, kk): c = chunk*CPB + kk/MIP, i = kk%MIP, value w2[c][i*MO+o]
template <int MI, int MIP, int MO>
__global__ void w2prep_kernel(const float* __restrict__ w2,
                              __nv_bfloat16* __restrict__ whi, __nv_bfloat16* __restrict__ wlo) {
    constexpr int CPB = 64 / MIP;
    constexpr int NCHUNK = 128 / CPB;
    int idx = blockIdx.x * blockDim.x + threadIdx.x;
    if (idx >= NCHUNK * MO * 64) return;
    int chunk = idx / (MO * 64);
    int rem = idx - chunk * MO * 64;
    int o = rem / 64;
    int kk = rem - o * 64;
    int c = chunk * CPB + kk / MIP;
    int i = kk % MIP;
    float v = (i < MI) ? w2[((size_t)c * MI + i) * MO + o] : 0.0f;
    __nv_bfloat16 h = __float2bfloat16(v);
    __nv_bfloat16 l = __float2bfloat16(v - __bfloat162float(h));
    int off = o * 128 + kk * 2;
    int sw = off ^ ((off >> 3) & 0x70);
    size_t dsti = (size_t)chunk * MO * 64 + (sw >> 1);
    whi[dsti] = h;
    wlo[dsti] = l;
}

// ---------------- out = x @ root + bias ----------------
template <int MI, int MO>
__global__ void root_kernel(const float* __restrict__ x, const float* __restrict__ root,
                            const float* __restrict__ bias, float* __restrict__ out) {
    int idx = blockIdx.x * blockDim.x + threadIdx.x;
    if (idx >= NNODES * MO) return;
    int n = idx / MO;
    int o = idx % MO;
    float acc = bias[o];
#pragma unroll
    for (int i = 0; i < MI; i++) acc += x[n * MI + i] * root[i * MO + o];
    out[idx] = acc;
}

// ---------------- b2 term: S[d] = sum_{e:dst=d} x[src[e]] ; out += S @ B2 ----------
__global__ void zero_kernel(float* __restrict__ p, int n) {
    int i = blockIdx.x * blockDim.x + threadIdx.x;
    if (i < n) p[i] = 0.0f;
}
template <int MI>
__global__ void scatter_x_kernel(const float* __restrict__ x, const int* __restrict__ src,
                                 const int* __restrict__ dst, float* __restrict__ S) {
    int idx = blockIdx.x * blockDim.x + threadIdx.x;
    if (idx >= NEDGES * MI) return;
    int e = idx / MI;
    int i = idx - e * MI;
    atomicAdd(&S[dst[e] * MI + i], x[src[e] * MI + i]);
}
template <int MI, int MO>
__global__ void sb2_kernel(const float* __restrict__ S, const float* __restrict__ b2,
                           float* __restrict__ out) {
    int idx = blockIdx.x * blockDim.x + threadIdx.x;
    if (idx >= NNODES * MO) return;
    int n = idx / MO;
    int o = idx - n * MO;
    float a = 0.0f;
#pragma unroll
    for (int i = 0; i < MI; i++) a += S[n * MI + i] * b2[i * MO + o];
    out[idx] += a;
}

// ================= HMMA (mma.sync bf16) edge-message GEMM + scatter-add =============
// Per block: 128 edges, 4 warps, each warp owns 32 edge-rows (2x m16 groups) and the
// full MO output columns, fp32 accumulators in registers. K processed in 64-wide
// bf16 chunks; P tile (hi/lo split) built on the fly into SW128-swizzled SMEM; W
// chunk is a straight vector copy of the pre-swizzled global image. 3 MMA passes
// (hi*hi, hi*lo, lo*hi) recover fp32 accuracy.
template <int MI, int MIP, int MO>
__global__ __launch_bounds__(128, 1)
void edge_mma_kernel(const float* __restrict__ ht, const float* __restrict__ x,
                     const __nv_bfloat16* __restrict__ whi, const __nv_bfloat16* __restrict__ wlo,
                     const int* __restrict__ src, const int* __restrict__ dst,
                     float* __restrict__ out) {
    constexpr int CPB = 64 / MIP;          // c-values per 64-col K chunk
    constexpr int NCHUNK = 128 / CPB;
    constexpr int NT = MO / 8;             // 8x8 n-tiles
    constexpr int OFF_X = 512;
    constexpr int OFF_PHI = OFF_X + MIP * 512;
    constexpr int OFF_WHI = OFF_PHI + 16384 * 2;
    constexpr int DLO = 16384;             // P lo-tile offset from hi
    constexpr int DWLO = MO * 128;         // W lo-image offset from hi

    extern __shared__ char smem[];
    const uint32_t sb = smem_to_u32(smem);
    const int tid = threadIdx.x;
    const int wid = tid >> 5;
    const int lane = tid & 31;
    const int e0 = blockIdx.x * 128;
    const int geT = min(e0 + tid, NEDGES - 1);

    // ---- gather this thread's edge x-row into SMEM transposed-pair layout [i/2][e] ----
    ull* xs2 = (ull*)(smem + OFF_X);
    {
        const int s = __ldg(&src[geT]);
#pragma unroll
        for (int j = 0; j < MIP / 2; j++) {
            int i0 = 2 * j;
            float v0 = (i0 < MI) ? __ldg(&x[(size_t)s * MI + i0]) : 0.0f;
            float v1 = (i0 + 1 < MI) ? __ldg(&x[(size_t)s * MI + i0 + 1]) : 0.0f;
            ull pv;
            asm("mov.b64 %0, {%1, %2};" : "=l"(pv) : "f"(v0), "f"(v1));
            xs2[j * 128 + tid] = pv;
        }
    }

    // ---- lane-constant ldmatrix addressing ----
    const int we = wid * 32;
    const int alrow = lane & 15;                    // A row within m16 group
    const int alk = (lane >> 4) << 4;               // A k byte offset (0/16)
    const uint32_t axor = (uint32_t)((alrow & 7) << 4);
    uint32_t abase0 = sb + OFF_PHI + (we + alrow) * 128;
    uint32_t abase1 = abase0 + 16 * 128;
    const int bl8 = lane & 7;
    const int bk = ((lane >> 3) & 1) << 4;          // B k byte offset (0/16)
    const int bn16 = (lane >> 4) << 3;              // B n offset within 16-group
    const uint32_t bxor = (uint32_t)(bl8 << 4);

    float acc[2][NT][4];
#pragma unroll
    for (int rg = 0; rg < 2; rg++)
#pragma unroll
        for (int nt = 0; nt < NT; nt++)
#pragma unroll
            for (int q = 0; q < 4; q++) acc[rg][nt][q] = 0.0f;

    const uint32_t phbase = sb + OFF_PHI + tid * 128;
    const uint32_t xorv = (uint32_t)((tid & 7) << 4);
    const ull m1 = pack2(-1.0f);

#pragma unroll 1
    for (int cc = 0; cc < NCHUNK; cc++) {
        // ---- W tiles: straight vector copy of pre-swizzled image ----
        {
            const uint4* gh = (const uint4*)whi + (size_t)cc * (MO * 8);
            const uint4* gl = (const uint4*)wlo + (size_t)cc * (MO * 8);
            uint4* sh = (uint4*)(smem + OFF_WHI);
            uint4* sl = (uint4*)(smem + OFF_WHI + DWLO);
#pragma unroll
            for (int t = tid; t < MO * 8; t += 128) {
                sh[t] = __ldg(&gh[t]);
                sl[t] = __ldg(&gl[t]);
            }
        }
        // ---- P tile build: row e = tid; hi = RZ-truncate, lo = exact residue ----
#pragma unroll
        for (int cl = 0; cl < CPB; cl++) {
            int c = cc * CPB + cl;
            float hv = __ldg(&ht[(size_t)c * NEDGES + geT]);
            ull hv2 = pack2(hv);
#pragma unroll
            for (int i = 0; i < MIP; i += 4) {
                ull x01 = xs2[(i >> 1) * 128 + tid];
                ull x23 = xs2[((i >> 1) + 1) * 128 + tid];
                ull pa = mul2(hv2, x01);
                ull pb = mul2(hv2, x23);
                ull pah = pa & 0xFFFF0000FFFF0000ULL;
                ull pbh = pb & 0xFFFF0000FFFF0000ULL;
                unsigned a0, a1, b0, b1;
                unpack2(pa, a0, a1);
                unpack2(pb, b0, b1);
                unsigned h0 = prmt7632(a0, a1);
                unsigned h1 = prmt7632(b0, b1);
                ull la = pa, lb = pb;
                ffma2(la, pah, m1);   // la = pa - pah (exact residue)
                ffma2(lb, pbh, m1);
                unsigned l0, l1, l2, l3;
                unpack2(la, l0, l1);
                unpack2(lb, l2, l3);
                unsigned q0, q1;
                CVT_BF16X2(q0, __uint_as_float(l0), __uint_as_float(l1));
                CVT_BF16X2(q1, __uint_as_float(l2), __uint_as_float(l3));
                uint32_t sa = ((uint32_t)((cl * MIP + i) * 2)) ^ xorv;
                STSV2(phbase + sa, h0, h1);
                STSV2(phbase + DLO + sa, q0, q1);
            }
        }
        __syncthreads();

        // ---- MMA: 4 k-steps of 16, 3 split passes ----
#pragma unroll
        for (int ks = 0; ks < 4; ks++) {
            const int kb = ks * 32;
            uint32_t ah[2][4], al[2][4];
            {
                uint32_t aoff = (uint32_t)(kb + alk) ^ axor;
                LDSM4(ah[0], abase0 + aoff);
                LDSM4(al[0], abase0 + aoff + DLO);
                LDSM4(ah[1], abase1 + aoff);
                LDSM4(al[1], abase1 + aoff + DLO);
            }
            uint32_t bh[NT][2], bl[NT][2];
#pragma unroll
            for (int g = 0; g < NT / 2; g++) {
                uint32_t baddr = sb + OFF_WHI + (uint32_t)((g * 16 + bn16 + bl8) * 128)
                               + ((uint32_t)(kb + bk) ^ bxor);
                uint32_t r[4];
                LDSM4(r, baddr);
                bh[2 * g][0] = r[0]; bh[2 * g][1] = r[1];
                bh[2 * g + 1][0] = r[2]; bh[2 * g + 1][1] = r[3];
                LDSM4(r, baddr + DWLO);
                bl[2 * g][0] = r[0]; bl[2 * g][1] = r[1];
                bl[2 * g + 1][0] = r[2]; bl[2 * g + 1][1] = r[3];
            }
#pragma unroll
            for (int rg = 0; rg < 2; rg++)
#pragma unroll
                for (int nt = 0; nt < NT; nt++) {
                    MMA_BF16(acc[rg][nt], ah[rg], bh[nt]);
                    MMA_BF16(acc[rg][nt], ah[rg], bl[nt]);
                    MMA_BF16(acc[rg][nt], al[rg], bh[nt]);
                }
        }
        __syncthreads();
    }

    // ---- epilogue: register accumulators -> atomic scatter-add ----
#pragma unroll
    for (int rg = 0; rg < 2; rg++) {
        int ea2 = e0 + we + rg * 16 + (lane >> 2);
        int eb2 = ea2 + 8;
        int da = (ea2 < NEDGES) ? dst[ea2] : -1;
        int db = (eb2 < NEDGES) ? dst[eb2] : -1;
#pragma unroll
        for (int nt = 0; nt < NT; nt++) {
            int col = nt * 8 + (lane & 3) * 2;
            if (da >= 0) {
                atomicAdd(&out[(size_t)da * MO + col],     acc[rg][nt][0]);
                atomicAdd(&out[(size_t)da * MO + col + 1], acc[rg][nt][1]);
            }
            if (db >= 0) {
                atomicAdd(&out[(size_t)db * MO + col],     acc[rg][nt][2]);
                atomicAdd(&out[(size_t)db * MO + col + 1], acc[rg][nt][3]);
            }
        }
    }
}

// ---------------- elementwise ELU (in place) ----------------
__global__ void elu_kernel(float* __restrict__ x, int n) {
    int i = blockIdx.x * blockDim.x + threadIdx.x;
    if (i >= n) return;
    float v = x[i];
    x[i] = v > 0.0f ? v : (expf(v) - 1.0f);
}

// ---------------- pooling ----------------
__global__ void zero_pool_kernel() {
    int i = blockIdx.x * blockDim.x + threadIdx.x;
    if (i < NGRAPH * 64) g_pool[i] = 0.0f;
    if (i < NGRAPH) g_cnt[i] = 0.0f;
}
__global__ void pool_kernel(const float* __restrict__ x, const int* __restrict__ batch) {
    int idx = blockIdx.x * blockDim.x + threadIdx.x;
    if (idx >= NNODES * 64) return;
    int n = idx >> 6;
    int o = idx & 63;
    int g = batch[n];
    atomicAdd(&g_pool[g * 64 + o], x[idx]);
    if (o == 0) atomicAdd(&g_cnt[g], 1.0f);
}

// ---------------- per-graph MLP head ----------------
__global__ void mlp_kernel(const float* __restrict__ fc1w, const float* __restrict__ fc1b,
                           const float* __restrict__ fc2w, const float* __restrict__ fc2b,
                           const float* __restrict__ fc3w, const float* __restrict__ fc3b,
                           float* __restrict__ out) {
    __shared__ float xg[64];
    __shared__ float y1[32];
    __shared__ float y2[16];
    int g = blockIdx.x;
    int t = threadIdx.x;
    float c = fmaxf(g_cnt[g], 1.0f);
    xg[t] = g_pool[g * 64 + t] / c;
    __syncthreads();
    if (t < 32) {
        float a = fc1b[t];
#pragma unroll
        for (int i = 0; i < 64; i++) a += xg[i] * fc1w[i * 32 + t];
        y1[t] = a > 0.0f ? a : (expf(a) - 1.0f);
    }
    __syncthreads();
    if (t < 16) {
        float a = fc2b[t];
#pragma unroll
        for (int i = 0; i < 32; i++) a += y1[i] * fc2w[i * 16 + t];
        y2[t] = a > 0.0f ? a : (expf(a) - 1.0f);
    }
    __syncthreads();
    if (t == 0) {
        float a = fc3b[0];
#pragma unroll
        for (int i = 0; i < 16; i++) a += y2[i] * fc3w[i];
        out[g] = a;
    }
}

// ---------------- launch ----------------
extern "C" void kernel_launch(void* const* d_in, const int* in_sizes, int n_in,
                              void* d_out, int out_size) {
    const float* x_in  = (const float*)d_in[0];
    const int*   ei    = (const int*)d_in[1];
    const float* ea    = (const float*)d_in[2];
    const int*   batch = (const int*)d_in[3];

    const float* w1[3]   = {(const float*)d_in[4],  (const float*)d_in[10], (const float*)d_in[16]};
    const float* b1[3]   = {(const float*)d_in[5],  (const float*)d_in[11], (const float*)d_in[17]};
    const float* w2[3]   = {(const float*)d_in[6],  (const float*)d_in[12], (const float*)d_in[18]};
    const float* b2[3]   = {(const float*)d_in[7],  (const float*)d_in[13], (const float*)d_in[19]};
    const float* root[3] = {(const float*)d_in[8],  (const float*)d_in[14], (const float*)d_in[20]};
    const float* bias[3] = {(const float*)d_in[9],  (const float*)d_in[15], (const float*)d_in[21]};

    const float* fc1w = (const float*)d_in[22];
    const float* fc1b = (const float*)d_in[23];
    const float* fc2w = (const float*)d_in[24];
    const float* fc2b = (const float*)d_in[25];
    const float* fc3w = (const float*)d_in[26];
    const float* fc3b = (const float*)d_in[27];

    const int* src = ei;
    const int* dst = ei + NEDGES;

    float *ht, *bufA, *bufB, *Sbuf;
    __nv_bfloat16 *whi, *wlo;
    cudaGetSymbolAddress((void**)&ht,   g_ht);
    cudaGetSymbolAddress((void**)&bufA, g_bufA);
    cudaGetSymbolAddress((void**)&bufB, g_bufB);
    cudaGetSymbolAddress((void**)&Sbuf, g_S);
    cudaGetSymbolAddress((void**)&whi,  g_w2t_hi);
    cudaGetSymbolAddress((void**)&wlo,  g_w2t_lo);

    // dynamic SMEM totals (must match in-kernel constexpr layout)
    const int SZ0 = 512 + 16 * 512 + 16384 * 2 + 32 * 128 * 2;   // 49664
    const int SZ1 = 512 + 32 * 512 + 16384 * 2 + 64 * 128 * 2;   // 66048
    const int SZ2 = 512 + 64 * 512 + 16384 * 2 + 64 * 128 * 2;   // 82432
    cudaFuncSetAttribute(edge_mma_kernel<13, 16, 32>,
                         cudaFuncAttributeMaxDynamicSharedMemorySize, SZ0);
    cudaFuncSetAttribute(edge_mma_kernel<32, 32, 64>,
                         cudaFuncAttributeMaxDynamicSharedMemorySize, SZ1);
    cudaFuncSetAttribute(edge_mma_kernel<64, 64, 64>,
                         cudaFuncAttributeMaxDynamicSharedMemorySize, SZ2);

    const int HT = (128 * NEDGES + 255) / 256;

    // ---- layer 0: 13 -> 32 ----
    h_kernel<<<HT, 256>>>(ea, w1[0], b1[0], ht);
    w2prep_kernel<13, 16, 32><<<(32 * 32 * 64 + 255) / 256, 256>>>(w2[0], whi, wlo);
    root_kernel<13, 32><<<(NNODES * 32 + 255) / 256, 256>>>(x_in, root[0], bias[0], bufA);
    zero_kernel<<<(NNODES * 13 + 255) / 256, 256>>>(Sbuf, NNODES * 13);
    scatter_x_kernel<13><<<(NEDGES * 13 + 255) / 256, 256>>>(x_in, src, dst, Sbuf);
    sb2_kernel<13, 32><<<(NNODES * 32 + 255) / 256, 256>>>(Sbuf, b2[0], bufA);
    edge_mma_kernel<13, 16, 32><<<EBLKS, 128, SZ0>>>(ht, x_in, whi, wlo, src, dst, bufA);
    elu_kernel<<<(NNODES * 32 + 255) / 256, 256>>>(bufA, NNODES * 32);

    // ---- layer 1: 32 -> 64 ----
    h_kernel<<<HT, 256>>>(ea, w1[1], b1[1], ht);
    w2prep_kernel<32, 32, 64><<<(64 * 64 * 64 + 255) / 256, 256>>>(w2[1], whi, wlo);
    root_kernel<32, 64><<<(NNODES * 64 + 255) / 256, 256>>>(bufA, root[1], bias[1], bufB);
    zero_kernel<<<(NNODES * 32 + 255) / 256, 256>>>(Sbuf, NNODES * 32);
    scatter_x_kernel<32><<<(NEDGES * 32 + 255) / 256, 256>>>(bufA, src, dst, Sbuf);
    sb2_kernel<32, 64><<<(NNODES * 64 + 255) / 256, 256>>>(Sbuf, b2[1], bufB);
    edge_mma_kernel<32, 32, 64><<<EBLKS, 128, SZ1>>>(ht, bufA, whi, wlo, src, dst, bufB);
    elu_kernel<<<(NNODES * 64 + 255) / 256, 256>>>(bufB, NNODES * 64);

    // ---- layer 2: 64 -> 64 ----
    h_kernel<<<HT, 256>>>(ea, w1[2], b1[2], ht);
    w2prep_kernel<64, 64, 64><<<(128 * 64 * 64 + 255) / 256, 256>>>(w2[2], whi, wlo);
    root_kernel<64, 64><<<(NNODES * 64 + 255) / 256, 256>>>(bufB, root[2], bias[2], bufA);
    zero_kernel<<<(NNODES * 64 + 255) / 256, 256>>>(Sbuf, NNODES * 64);
    scatter_x_kernel<64><<<(NEDGES * 64 + 255) / 256, 256>>>(bufB, src, dst, Sbuf);
    sb2_kernel<64, 64><<<(NNODES * 64 + 255) / 256, 256>>>(Sbuf, b2[2], bufA);
    edge_mma_kernel<64, 64, 64><<<EBLKS, 128, SZ2>>>(ht, bufB, whi, wlo, src, dst, bufA);
    elu_kernel<<<(NNODES * 64 + 255) / 256, 256>>>(bufA, NNODES * 64);

    // ---- pooling + MLP head ----
    zero_pool_kernel<<<(NGRAPH * 64 + 255) / 256, 256>>>();
    pool_kernel<<<(NNODES * 64 + 255) / 256, 256>>>(bufA, batch);
    mlp_kernel<<<NGRAPH, 64>>>(fc1w, fc1b, fc2w, fc2b, fc3w, fc3b, (float*)d_out);
}